// round 6
// baseline (speedup 1.0000x reference)
#include <cuda_runtime.h>
#include <cstdint>
#include <cstddef>

// ---------------- static problem shape ----------------
constexpr int BSZ = 2;
constexpr int NQ  = 21760;
constexpr int MR  = BSZ * NQ;      // 43520 rows
constexpr int D   = 256;
constexpr int NH  = 8;
constexpr int DH  = 32;
constexpr int NFUSED = 384;        // 256 offs + 128 attn logits

__device__ __constant__ int c_LW[4] = {128, 64, 32, 16};
__device__ __constant__ int c_LH[4] = {128, 64, 32, 16};
__device__ __constant__ int c_LS[4] = {0, 16384, 20480, 21504};

// ---------------- scratch ----------------
__device__ float  g_vt[(size_t)BSZ * NH * NQ * DH];     // v transposed: [b][h][pos][c]
__device__ float  g_P [(size_t)MR * NFUSED];            // raw offs(256) + attn logits(128)
__device__ float  g_tmp[(size_t)MR * D];                // attention output before Wout
__device__ float  g_Wf[D * NFUSED];                     // fused [Wo | Wa]
__device__ float  g_bf[NFUSED];                         // fused [bo | ba]

// ---------------- helpers ----------------
__device__ __forceinline__ void mma_tf32(float& c0, float& c1, float& c2, float& c3,
                                         uint32_t a0, uint32_t a1, uint32_t a2, uint32_t a3,
                                         uint32_t b0, uint32_t b1) {
    asm volatile(
        "mma.sync.aligned.m16n8k8.row.col.f32.tf32.tf32.f32 "
        "{%0,%1,%2,%3}, {%4,%5,%6,%7}, {%8,%9}, {%0,%1,%2,%3};"
        : "+f"(c0), "+f"(c1), "+f"(c2), "+f"(c3)
        : "r"(a0), "r"(a1), "r"(a2), "r"(a3), "r"(b0), "r"(b1));
}

__device__ __forceinline__ void cp16(void* smem_dst, const void* gsrc) {
    unsigned d = (unsigned)__cvta_generic_to_shared(smem_dst);
    asm volatile("cp.async.cg.shared.global [%0], [%1], 16;" :: "r"(d), "l"(gsrc));
}

// ---------------- pack fused weight ----------------
__global__ void pack_w_kernel(const float* __restrict__ Wo, const float* __restrict__ bo,
                              const float* __restrict__ Wa, const float* __restrict__ ba) {
    int i = blockIdx.x * blockDim.x + threadIdx.x;
    if (i < D * NFUSED) {
        int k = i / NFUSED, n = i % NFUSED;
        g_Wf[i] = (n < 256) ? Wo[k * 256 + n] : Wa[k * 128 + (n - 256)];
    }
    if (i < NFUSED) g_bf[i] = (i < 256) ? bo[i] : ba[i - 256];
}

// ---------------- tf32 tensor-core GEMM, cp.async double-buffered ----------------
// Tile: BM=128, BN=64, BK=16.  8 warps as 4(M) x 2(N), warp tile 32x32.
// Raw fp32 bits fed to mma.tf32 (no cvt in hot loop; HW truncates mantissa).
// MODE 0: A=value, W=Wv   -> scatter into g_vt [b][h][pos][c]
// MODE 1: A=query, W=g_Wf -> g_P row-major
// MODE 2: A=g_tmp, W=Wout -> Cout = acc + bias + addin (residual)
template<int MODE>
__global__ __launch_bounds__(256)
void gemm_tc(const float* __restrict__ Ain, const float* __restrict__ Win,
             const float* __restrict__ biasin, const float* __restrict__ addin,
             float* __restrict__ Cout, int N)
{
    constexpr int K = D;
    const float* A    = (MODE == 2) ? g_tmp : Ain;
    const float* W    = (MODE == 1) ? g_Wf  : Win;
    const float* bias = (MODE == 1) ? g_bf  : biasin;

    __shared__ float As[2][128][20];   // [buf][m][k], stride 20 -> conflict-free
    __shared__ float Bs[2][16][72];    // [buf][k][n], stride 72 -> conflict-free

    const int tid  = threadIdx.x;
    const int warp = tid >> 5;
    const int lane = tid & 31;
    const int wm   = (warp & 3) * 32;
    const int wn   = (warp >> 2) * 32;
    const int m0   = blockIdx.x * 128;
    const int n0   = blockIdx.y * 64;

    const int ar = tid >> 2;   // 0..63 (and +64)
    const int aq = tid & 3;
    const int br = tid >> 4;   // 0..15
    const int bc = tid & 15;

    float c[2][4][4];
    #pragma unroll
    for (int mf = 0; mf < 2; ++mf)
        #pragma unroll
        for (int nf = 0; nf < 4; ++nf)
            #pragma unroll
            for (int i = 0; i < 4; ++i) c[mf][nf][i] = 0.f;

    auto load_stage = [&](int kt, int buf) {
        const int kk = kt * 16;
        cp16(&As[buf][ar][aq * 4],      A + (size_t)(m0 + ar) * K + kk + aq * 4);
        cp16(&As[buf][ar + 64][aq * 4], A + (size_t)(m0 + ar + 64) * K + kk + aq * 4);
        cp16(&Bs[buf][br][bc * 4],      W + (size_t)(kk + br) * N + n0 + bc * 4);
        asm volatile("cp.async.commit_group;" ::: "memory");
    };

    load_stage(0, 0);

    for (int kt = 0; kt < 16; ++kt) {
        const int buf = kt & 1;
        if (kt + 1 < 16) {
            load_stage(kt + 1, buf ^ 1);
            asm volatile("cp.async.wait_group 1;" ::: "memory");
        } else {
            asm volatile("cp.async.wait_group 0;" ::: "memory");
        }
        __syncthreads();

        #pragma unroll
        for (int kc = 0; kc < 16; kc += 8) {
            uint32_t a[2][4], b[4][2];
            const int arow = wm + (lane >> 2);
            const int acol = kc + (lane & 3);
            #pragma unroll
            for (int mf = 0; mf < 2; ++mf) {
                const int r0 = arow + mf * 16;
                a[mf][0] = __float_as_uint(As[buf][r0    ][acol    ]);
                a[mf][1] = __float_as_uint(As[buf][r0 + 8][acol    ]);
                a[mf][2] = __float_as_uint(As[buf][r0    ][acol + 4]);
                a[mf][3] = __float_as_uint(As[buf][r0 + 8][acol + 4]);
            }
            #pragma unroll
            for (int nf = 0; nf < 4; ++nf) {
                const int nn = wn + nf * 8 + (lane >> 2);
                b[nf][0] = __float_as_uint(Bs[buf][acol    ][nn]);
                b[nf][1] = __float_as_uint(Bs[buf][acol + 4][nn]);
            }
            #pragma unroll
            for (int mf = 0; mf < 2; ++mf)
                #pragma unroll
                for (int nf = 0; nf < 4; ++nf)
                    mma_tf32(c[mf][nf][0], c[mf][nf][1], c[mf][nf][2], c[mf][nf][3],
                             a[mf][0], a[mf][1], a[mf][2], a[mf][3],
                             b[nf][0], b[nf][1]);
        }
        __syncthreads();
    }

    // epilogue
    #pragma unroll
    for (int mf = 0; mf < 2; ++mf) {
        #pragma unroll
        for (int nf = 0; nf < 4; ++nf) {
            const int cb = n0 + wn + nf * 8 + 2 * (lane & 3);
            const float2 b2 = *reinterpret_cast<const float2*>(bias + cb);
            #pragma unroll
            for (int half = 0; half < 2; ++half) {
                const int row = m0 + wm + mf * 16 + (lane >> 2) + half * 8;
                const float v0 = c[mf][nf][half * 2 + 0] + b2.x;
                const float v1 = c[mf][nf][half * 2 + 1] + b2.y;
                if (MODE == 0) {
                    const int bb  = row / NQ;
                    const int pos = row - bb * NQ;
                    float2* dst = reinterpret_cast<float2*>(
                        g_vt + ((size_t)(bb * NH + (cb >> 5)) * NQ + pos) * DH + (cb & 31));
                    *dst = make_float2(v0, v1);
                } else if (MODE == 1) {
                    *reinterpret_cast<float2*>(g_P + (size_t)row * NFUSED + cb)
                        = make_float2(v0, v1);
                } else {
                    const float2 q2 = *reinterpret_cast<const float2*>(
                        addin + (size_t)row * D + cb);
                    *reinterpret_cast<float2*>(Cout + (size_t)row * D + cb)
                        = make_float2(v0 + q2.x, v1 + q2.y);
                }
            }
        }
    }
}

// ---------------- fused softmax + coords + bilinear gather ----------------
// Stage 1: lane i (0-15, mirrored on 16-31) owns point i: softmax, then 4
// clamped corner element-offsets + 4 validity-folded weights, all in REGISTERS.
// Stage 2: 4 point-groups of 8 lanes; per level: 8 shuffles bring the corner
// params, then 4 unconditional LDG.128 + 16 FFMA. No LDS/STS, no per-point
// recompute. Final xor-reduction over groups.
__global__ __launch_bounds__(256)
void sample_kernel(const float* __restrict__ refp) {
    const int gwarp = blockIdx.x * 8 + (threadIdx.x >> 5);
    const int lane  = threadIdx.x & 31;
    if (gwarp >= MR * NH) return;
    const int h  = gwarp & 7;
    const int bq = gwarp >> 3;
    const int b  = (bq >= NQ);

    const float* Prow = g_P + (size_t)bq * NFUSED;
    const int i  = lane & 15;          // point index (lanes 16-31 mirror)
    const int il = i >> 2;

    // softmax over the 16 logits of this head
    float lg = Prow[256 + h * 16 + i];
    float mx = lg;
    #pragma unroll
    for (int off = 8; off; off >>= 1)
        mx = fmaxf(mx, __shfl_xor_sync(0xffffffffu, mx, off));
    float e = __expf(lg - mx);
    float ssum = e;
    #pragma unroll
    for (int off = 8; off; off >>= 1)
        ssum += __shfl_xor_sync(0xffffffffu, ssum, off);
    const float wgt = e / ssum;

    // corner offsets + weights for this lane's point (registers only)
    int   o00, o01, o10, o11;
    float w00, w01, w10, w11;
    {
        const float2 off2 = *reinterpret_cast<const float2*>(Prow + h * 32 + i * 2);
        const float2 ref2 = *reinterpret_cast<const float2*>(refp + (size_t)bq * 8 + il * 2);
        const int Wl = c_LW[il], Hl = c_LH[il], st = c_LS[il];
        const float px = ref2.x * (float)Wl + off2.x - 0.5f;
        const float py = ref2.y * (float)Hl + off2.y - 0.5f;

        const float xf = floorf(px), yf = floorf(py);
        const int   x0 = (int)xf,    y0 = (int)yf;
        const int   x1 = x0 + 1,     y1 = y0 + 1;
        const float wx1 = px - xf,   wy1 = py - yf;
        const float wx0 = 1.f - wx1, wy0 = 1.f - wy1;
        const float vx0 = ((unsigned)x0 < (unsigned)Wl) ? 1.f : 0.f;
        const float vx1 = ((unsigned)x1 < (unsigned)Wl) ? 1.f : 0.f;
        const float vy0 = ((unsigned)y0 < (unsigned)Hl) ? 1.f : 0.f;
        const float vy1 = ((unsigned)y1 < (unsigned)Hl) ? 1.f : 0.f;
        const int cx0 = min(max(x0, 0), Wl - 1);
        const int cx1 = min(max(x1, 0), Wl - 1);
        const int cy0 = min(max(y0, 0), Hl - 1);
        const int cy1 = min(max(y1, 0), Hl - 1);
        const int r0 = st + cy0 * Wl;
        const int r1 = st + cy1 * Wl;
        o00 = (r0 + cx0) * DH;  w00 = wgt * wy0 * wx0 * vy0 * vx0;
        o01 = (r0 + cx1) * DH;  w01 = wgt * wy0 * wx1 * vy0 * vx1;
        o10 = (r1 + cx0) * DH;  w10 = wgt * wy1 * wx0 * vy1 * vx0;
        o11 = (r1 + cx1) * DH;  w11 = wgt * wy1 * wx1 * vy1 * vx1;
    }

    const int pgrp = lane >> 3;
    const int cq   = (lane & 7) * 4;
    const float* vb = g_vt + ((size_t)(b * NH + h) * NQ) * DH + cq;

    float4 acc = make_float4(0.f, 0.f, 0.f, 0.f);
    #pragma unroll
    for (int j = 0; j < 4; ++j) {      // j = level
        const int p = j * 4 + pgrp;
        const int   a00 = __shfl_sync(0xffffffffu, o00, p);
        const int   a01 = __shfl_sync(0xffffffffu, o01, p);
        const int   a10 = __shfl_sync(0xffffffffu, o10, p);
        const int   a11 = __shfl_sync(0xffffffffu, o11, p);
        const float s00 = __shfl_sync(0xffffffffu, w00, p);
        const float s01 = __shfl_sync(0xffffffffu, w01, p);
        const float s10 = __shfl_sync(0xffffffffu, w10, p);
        const float s11 = __shfl_sync(0xffffffffu, w11, p);
        const float4 v00 = *reinterpret_cast<const float4*>(vb + a00);
        const float4 v01 = *reinterpret_cast<const float4*>(vb + a01);
        const float4 v10 = *reinterpret_cast<const float4*>(vb + a10);
        const float4 v11 = *reinterpret_cast<const float4*>(vb + a11);
        acc.x += s00 * v00.x + s01 * v01.x + s10 * v10.x + s11 * v11.x;
        acc.y += s00 * v00.y + s01 * v01.y + s10 * v10.y + s11 * v11.y;
        acc.z += s00 * v00.z + s01 * v01.z + s10 * v10.z + s11 * v11.z;
        acc.w += s00 * v00.w + s01 * v01.w + s10 * v10.w + s11 * v11.w;
    }

    // reduce across the 4 point-groups (lanes xor 8, 16)
    #pragma unroll
    for (int off = 8; off <= 16; off <<= 1) {
        acc.x += __shfl_xor_sync(0xffffffffu, acc.x, off);
        acc.y += __shfl_xor_sync(0xffffffffu, acc.y, off);
        acc.z += __shfl_xor_sync(0xffffffffu, acc.z, off);
        acc.w += __shfl_xor_sync(0xffffffffu, acc.w, off);
    }
    if (lane < 8)
        *reinterpret_cast<float4*>(g_tmp + (size_t)bq * D + h * DH + cq) = acc;
}

// ---------------- launch ----------------
extern "C" void kernel_launch(void* const* d_in, const int* in_sizes, int n_in,
                              void* d_out, int out_size) {
    const float* query = (const float*)d_in[0];
    const float* value = (const float*)d_in[1];
    const float* refp  = (const float*)d_in[2];
    const float* Wv   = (const float*)d_in[5];
    const float* bv   = (const float*)d_in[6];
    const float* Wo   = (const float*)d_in[7];
    const float* bo   = (const float*)d_in[8];
    const float* Wa   = (const float*)d_in[9];
    const float* ba   = (const float*)d_in[10];
    const float* Wout = (const float*)d_in[11];
    const float* bout = (const float*)d_in[12];
    float* out = (float*)d_out;

    pack_w_kernel<<<(D * NFUSED + 255) / 256, 256>>>(Wo, bo, Wa, ba);

    gemm_tc<0><<<dim3(MR / 128, 256 / 64), 256>>>(value, Wv, bv, nullptr, nullptr, 256);
    gemm_tc<1><<<dim3(MR / 128, NFUSED / 64), 256>>>(query, nullptr, nullptr, nullptr, nullptr, NFUSED);

    sample_kernel<<<MR * NH / 8, 256>>>(refp);

    gemm_tc<2><<<dim3(MR / 128, 256 / 64), 256>>>(nullptr, Wout, bout, query, out, 256);
}

// round 7
// speedup vs baseline: 1.5395x; 1.5395x over previous
#include <cuda_runtime.h>
#include <cstdint>
#include <cstddef>

// ---------------- static problem shape ----------------
constexpr int BSZ = 2;
constexpr int NQ  = 21760;
constexpr int MR  = BSZ * NQ;      // 43520 rows
constexpr int D   = 256;
constexpr int NH  = 8;
constexpr int DH  = 32;
constexpr int NFUSED = 384;        // 256 offs + 128 attn logits

__device__ __constant__ int c_LW[4] = {128, 64, 32, 16};
__device__ __constant__ int c_LH[4] = {128, 64, 32, 16};
__device__ __constant__ int c_LS[4] = {0, 16384, 20480, 21504};

// ---------------- scratch ----------------
__device__ float  g_vt[(size_t)BSZ * NH * NQ * DH];     // v transposed: [b][h][pos][c]
__device__ float  g_P [(size_t)MR * NFUSED];            // raw offs(256) + attn logits(128)
__device__ float  g_tmp[(size_t)MR * D];                // attention output before Wout
__device__ float  g_Wf[D * NFUSED];                     // fused [Wo | Wa]
__device__ float  g_bf[NFUSED];                         // fused [bo | ba]

// ---------------- helpers ----------------
__device__ __forceinline__ uint32_t f2tf32(float x) {
    uint32_t r;
    asm("cvt.rna.tf32.f32 %0, %1;" : "=r"(r) : "f"(x));
    return r;
}

__device__ __forceinline__ void mma_tf32(float& c0, float& c1, float& c2, float& c3,
                                         uint32_t a0, uint32_t a1, uint32_t a2, uint32_t a3,
                                         uint32_t b0, uint32_t b1) {
    asm volatile(
        "mma.sync.aligned.m16n8k8.row.col.f32.tf32.tf32.f32 "
        "{%0,%1,%2,%3}, {%4,%5,%6,%7}, {%8,%9}, {%0,%1,%2,%3};"
        : "+f"(c0), "+f"(c1), "+f"(c2), "+f"(c3)
        : "r"(a0), "r"(a1), "r"(a2), "r"(a3), "r"(b0), "r"(b1));
}

__device__ __forceinline__ void cp16(void* smem_dst, const void* gsrc) {
    unsigned d = (unsigned)__cvta_generic_to_shared(smem_dst);
    asm volatile("cp.async.cg.shared.global [%0], [%1], 16;" :: "r"(d), "l"(gsrc));
}

// ---------------- pack fused weight ----------------
__global__ void pack_w_kernel(const float* __restrict__ Wo, const float* __restrict__ bo,
                              const float* __restrict__ Wa, const float* __restrict__ ba) {
    int i = blockIdx.x * blockDim.x + threadIdx.x;
    if (i < D * NFUSED) {
        int k = i / NFUSED, n = i % NFUSED;
        g_Wf[i] = (n < 256) ? Wo[k * 256 + n] : Wa[k * 128 + (n - 256)];
    }
    if (i < NFUSED) g_bf[i] = (i < 256) ? bo[i] : ba[i - 256];
}

// ---------------- tf32 tensor-core GEMM, cp.async double-buffered ----------------
// Tile: BM=128, BN=64, BK=16.  8 warps as 4(M) x 2(N), warp tile 32x32.
// A fragments: cvt.rna.tf32 (round-to-nearest).  B fragments: raw fp32 bits
// (HW truncates mantissa) -- halves the cvt count in the hot loop.
// MODE 0: A=value, W=Wv   -> scatter into g_vt [b][h][pos][c]
// MODE 1: A=query, W=g_Wf -> g_P row-major
// MODE 2: A=g_tmp, W=Wout -> Cout = acc + bias + addin (residual)
template<int MODE>
__global__ __launch_bounds__(256)
void gemm_tc(const float* __restrict__ Ain, const float* __restrict__ Win,
             const float* __restrict__ biasin, const float* __restrict__ addin,
             float* __restrict__ Cout, int N)
{
    constexpr int K = D;
    const float* A    = (MODE == 2) ? g_tmp : Ain;
    const float* W    = (MODE == 1) ? g_Wf  : Win;
    const float* bias = (MODE == 1) ? g_bf  : biasin;

    __shared__ float As[2][128][20];   // [buf][m][k], stride 20 -> conflict-free
    __shared__ float Bs[2][16][72];    // [buf][k][n], stride 72 -> conflict-free

    const int tid  = threadIdx.x;
    const int warp = tid >> 5;
    const int lane = tid & 31;
    const int wm   = (warp & 3) * 32;
    const int wn   = (warp >> 2) * 32;
    const int m0   = blockIdx.x * 128;
    const int n0   = blockIdx.y * 64;

    const int ar = tid >> 2;   // 0..63 (and +64)
    const int aq = tid & 3;
    const int br = tid >> 4;   // 0..15
    const int bc = tid & 15;

    float c[2][4][4];
    #pragma unroll
    for (int mf = 0; mf < 2; ++mf)
        #pragma unroll
        for (int nf = 0; nf < 4; ++nf)
            #pragma unroll
            for (int i = 0; i < 4; ++i) c[mf][nf][i] = 0.f;

    auto load_stage = [&](int kt, int buf) {
        const int kk = kt * 16;
        cp16(&As[buf][ar][aq * 4],      A + (size_t)(m0 + ar) * K + kk + aq * 4);
        cp16(&As[buf][ar + 64][aq * 4], A + (size_t)(m0 + ar + 64) * K + kk + aq * 4);
        cp16(&Bs[buf][br][bc * 4],      W + (size_t)(kk + br) * N + n0 + bc * 4);
        asm volatile("cp.async.commit_group;" ::: "memory");
    };

    load_stage(0, 0);

    for (int kt = 0; kt < 16; ++kt) {
        const int buf = kt & 1;
        if (kt + 1 < 16) {
            load_stage(kt + 1, buf ^ 1);
            asm volatile("cp.async.wait_group 1;" ::: "memory");
        } else {
            asm volatile("cp.async.wait_group 0;" ::: "memory");
        }
        __syncthreads();

        #pragma unroll
        for (int kc = 0; kc < 16; kc += 8) {
            uint32_t a[2][4], b[4][2];
            const int arow = wm + (lane >> 2);
            const int acol = kc + (lane & 3);
            #pragma unroll
            for (int mf = 0; mf < 2; ++mf) {
                const int r0 = arow + mf * 16;
                a[mf][0] = f2tf32(As[buf][r0    ][acol    ]);
                a[mf][1] = f2tf32(As[buf][r0 + 8][acol    ]);
                a[mf][2] = f2tf32(As[buf][r0    ][acol + 4]);
                a[mf][3] = f2tf32(As[buf][r0 + 8][acol + 4]);
            }
            #pragma unroll
            for (int nf = 0; nf < 4; ++nf) {
                const int nn = wn + nf * 8 + (lane >> 2);
                b[nf][0] = __float_as_uint(Bs[buf][acol    ][nn]);
                b[nf][1] = __float_as_uint(Bs[buf][acol + 4][nn]);
            }
            #pragma unroll
            for (int mf = 0; mf < 2; ++mf)
                #pragma unroll
                for (int nf = 0; nf < 4; ++nf)
                    mma_tf32(c[mf][nf][0], c[mf][nf][1], c[mf][nf][2], c[mf][nf][3],
                             a[mf][0], a[mf][1], a[mf][2], a[mf][3],
                             b[nf][0], b[nf][1]);
        }
        __syncthreads();
    }

    // epilogue
    #pragma unroll
    for (int mf = 0; mf < 2; ++mf) {
        #pragma unroll
        for (int nf = 0; nf < 4; ++nf) {
            const int cb = n0 + wn + nf * 8 + 2 * (lane & 3);
            const float2 b2 = *reinterpret_cast<const float2*>(bias + cb);
            #pragma unroll
            for (int half = 0; half < 2; ++half) {
                const int row = m0 + wm + mf * 16 + (lane >> 2) + half * 8;
                const float v0 = c[mf][nf][half * 2 + 0] + b2.x;
                const float v1 = c[mf][nf][half * 2 + 1] + b2.y;
                if (MODE == 0) {
                    const int bb  = row / NQ;
                    const int pos = row - bb * NQ;
                    float2* dst = reinterpret_cast<float2*>(
                        g_vt + ((size_t)(bb * NH + (cb >> 5)) * NQ + pos) * DH + (cb & 31));
                    *dst = make_float2(v0, v1);
                } else if (MODE == 1) {
                    *reinterpret_cast<float2*>(g_P + (size_t)row * NFUSED + cb)
                        = make_float2(v0, v1);
                } else {
                    const float2 q2 = *reinterpret_cast<const float2*>(
                        addin + (size_t)row * D + cb);
                    *reinterpret_cast<float2*>(Cout + (size_t)row * D + cb)
                        = make_float2(v0 + q2.x, v1 + q2.y);
                }
            }
        }
    }
}

// ---------------- fused softmax + coords + bilinear gather ----------------
// R3 structure (measured best): Stage 1: lane i<16 owns point i -> softmax+coords.
// Stage 2: 4 point-groups of 8 lanes; per level 3 broadcast shuffles + per-group
// ALU recompute of corner math + 4 predicated LDG.128.  Aux work stays on the
// ALU pipe, off the MIO pipe.  Final xor-reduction over groups.
__global__ __launch_bounds__(256)
void sample_kernel(const float* __restrict__ refp) {
    const int gwarp = blockIdx.x * 8 + (threadIdx.x >> 5);
    const int lane  = threadIdx.x & 31;
    if (gwarp >= MR * NH) return;
    const int h  = gwarp & 7;
    const int bq = gwarp >> 3;
    const int b  = (bq >= NQ);

    const float* Prow = g_P + (size_t)bq * NFUSED;
    const int i  = lane & 15;          // point index (lanes 16-31 mirror)
    const int il = i >> 2;

    // softmax over the 16 logits of this head
    float lg = Prow[256 + h * 16 + i];
    float mx = lg;
    #pragma unroll
    for (int off = 8; off; off >>= 1)
        mx = fmaxf(mx, __shfl_xor_sync(0xffffffffu, mx, off));
    float e = __expf(lg - mx);
    float ssum = e;
    #pragma unroll
    for (int off = 8; off; off >>= 1)
        ssum += __shfl_xor_sync(0xffffffffu, ssum, off);
    const float wgt = e / ssum;

    // pixel coords for this lane's point
    const float2 off2 = *reinterpret_cast<const float2*>(Prow + h * 32 + i * 2);
    const float2 ref2 = *reinterpret_cast<const float2*>(refp + (size_t)bq * 8 + il * 2);
    const float px = ref2.x * (float)c_LW[il] + off2.x - 0.5f;
    const float py = ref2.y * (float)c_LH[il] + off2.y - 0.5f;

    const int pgrp = lane >> 3;       // which point of the level this group does
    const int cq   = (lane & 7) * 4;  // channel quad
    const float* vb = g_vt + ((size_t)(b * NH + h) * NQ) * DH + cq;

    float4 acc = make_float4(0.f, 0.f, 0.f, 0.f);
    #pragma unroll
    for (int j = 0; j < 4; ++j) {     // j = level
        const int Wl = c_LW[j], Hl = c_LH[j], st = c_LS[j];
        const int p  = j * 4 + pgrp;
        const float sx = __shfl_sync(0xffffffffu, px,  p);
        const float sy = __shfl_sync(0xffffffffu, py,  p);
        const float sw = __shfl_sync(0xffffffffu, wgt, p);

        const float xf = floorf(sx), yf = floorf(sy);
        const int   x0 = (int)xf,    y0 = (int)yf;
        const float wx1 = sx - xf,   wy1 = sy - yf;
        const float wx0 = 1.f - wx1, wy0 = 1.f - wy1;
        const int x1 = x0 + 1, y1 = y0 + 1;
        const bool vx0 = (x0 >= 0) && (x0 < Wl);
        const bool vx1 = (x1 >= 0) && (x1 < Wl);
        const bool vy0 = (y0 >= 0) && (y0 < Hl);
        const bool vy1 = (y1 >= 0) && (y1 < Hl);

        const float w00 = sw * wy0 * wx0;
        const float w01 = sw * wy0 * wx1;
        const float w10 = sw * wy1 * wx0;
        const float w11 = sw * wy1 * wx1;

        float4 v00 = make_float4(0,0,0,0), v01 = v00, v10 = v00, v11 = v00;
        const float* r0 = vb + (size_t)(st + y0 * Wl) * DH;
        const float* r1 = vb + (size_t)(st + y1 * Wl) * DH;
        if (vy0 && vx0) v00 = *reinterpret_cast<const float4*>(r0 + (size_t)x0 * DH);
        if (vy0 && vx1) v01 = *reinterpret_cast<const float4*>(r0 + (size_t)x1 * DH);
        if (vy1 && vx0) v10 = *reinterpret_cast<const float4*>(r1 + (size_t)x0 * DH);
        if (vy1 && vx1) v11 = *reinterpret_cast<const float4*>(r1 + (size_t)x1 * DH);

        acc.x += w00 * v00.x + w01 * v01.x + w10 * v10.x + w11 * v11.x;
        acc.y += w00 * v00.y + w01 * v01.y + w10 * v10.y + w11 * v11.y;
        acc.z += w00 * v00.z + w01 * v01.z + w10 * v10.z + w11 * v11.z;
        acc.w += w00 * v00.w + w01 * v01.w + w10 * v10.w + w11 * v11.w;
    }

    // reduce across the 4 point-groups (lanes xor 8, 16)
    #pragma unroll
    for (int off = 8; off <= 16; off <<= 1) {
        acc.x += __shfl_xor_sync(0xffffffffu, acc.x, off);
        acc.y += __shfl_xor_sync(0xffffffffu, acc.y, off);
        acc.z += __shfl_xor_sync(0xffffffffu, acc.z, off);
        acc.w += __shfl_xor_sync(0xffffffffu, acc.w, off);
    }
    if (lane < 8)
        *reinterpret_cast<float4*>(g_tmp + (size_t)bq * D + h * DH + cq) = acc;
}

// ---------------- launch ----------------
extern "C" void kernel_launch(void* const* d_in, const int* in_sizes, int n_in,
                              void* d_out, int out_size) {
    const float* query = (const float*)d_in[0];
    const float* value = (const float*)d_in[1];
    const float* refp  = (const float*)d_in[2];
    const float* Wv   = (const float*)d_in[5];
    const float* bv   = (const float*)d_in[6];
    const float* Wo   = (const float*)d_in[7];
    const float* bo   = (const float*)d_in[8];
    const float* Wa   = (const float*)d_in[9];
    const float* ba   = (const float*)d_in[10];
    const float* Wout = (const float*)d_in[11];
    const float* bout = (const float*)d_in[12];
    float* out = (float*)d_out;

    pack_w_kernel<<<(D * NFUSED + 255) / 256, 256>>>(Wo, bo, Wa, ba);

    gemm_tc<0><<<dim3(MR / 128, 256 / 64), 256>>>(value, Wv, bv, nullptr, nullptr, 256);
    gemm_tc<1><<<dim3(MR / 128, NFUSED / 64), 256>>>(query, nullptr, nullptr, nullptr, nullptr, NFUSED);

    sample_kernel<<<MR * NH / 8, 256>>>(refp);

    gemm_tc<2><<<dim3(MR / 128, 256 / 64), 256>>>(nullptr, Wout, bout, query, out, 256);
}

// round 8
// speedup vs baseline: 1.6482x; 1.0706x over previous
#include <cuda_runtime.h>
#include <cstdint>
#include <cstddef>

// ---------------- static problem shape ----------------
constexpr int BSZ = 2;
constexpr int NQ  = 21760;
constexpr int MR  = BSZ * NQ;      // 43520 rows
constexpr int D   = 256;
constexpr int NH  = 8;
constexpr int DH  = 32;
constexpr int NFUSED = 384;        // 256 offs + 128 attn logits

__device__ __constant__ int c_LW[4] = {128, 64, 32, 16};
__device__ __constant__ int c_LH[4] = {128, 64, 32, 16};
__device__ __constant__ int c_LS[4] = {0, 16384, 20480, 21504};

// ---------------- scratch ----------------
__device__ float  g_vt[(size_t)BSZ * NH * NQ * DH];     // v transposed: [b][h][pos][c]
__device__ float  g_P [(size_t)MR * NFUSED];            // raw offs(256) + attn logits(128)
__device__ float  g_tmp[(size_t)MR * D];                // attention output before Wout
__device__ float  g_Wf[D * NFUSED];                     // fused [Wo | Wa]
__device__ float  g_bf[NFUSED];                         // fused [bo | ba]

// ---------------- helpers ----------------
__device__ __forceinline__ void mma_tf32(float& c0, float& c1, float& c2, float& c3,
                                         uint32_t a0, uint32_t a1, uint32_t a2, uint32_t a3,
                                         uint32_t b0, uint32_t b1) {
    asm volatile(
        "mma.sync.aligned.m16n8k8.row.col.f32.tf32.tf32.f32 "
        "{%0,%1,%2,%3}, {%4,%5,%6,%7}, {%8,%9}, {%0,%1,%2,%3};"
        : "+f"(c0), "+f"(c1), "+f"(c2), "+f"(c3)
        : "r"(a0), "r"(a1), "r"(a2), "r"(a3), "r"(b0), "r"(b1));
}

__device__ __forceinline__ void cp16(void* smem_dst, const void* gsrc) {
    unsigned d = (unsigned)__cvta_generic_to_shared(smem_dst);
    asm volatile("cp.async.cg.shared.global [%0], [%1], 16;" :: "r"(d), "l"(gsrc));
}

// ---------------- pack fused weight ----------------
__global__ void pack_w_kernel(const float* __restrict__ Wo, const float* __restrict__ bo,
                              const float* __restrict__ Wa, const float* __restrict__ ba) {
    int i = blockIdx.x * blockDim.x + threadIdx.x;
    if (i < D * NFUSED) {
        int k = i / NFUSED, n = i % NFUSED;
        g_Wf[i] = (n < 256) ? Wo[k * 256 + n] : Wa[k * 128 + (n - 256)];
    }
    if (i < NFUSED) g_bf[i] = (i < 256) ? bo[i] : ba[i - 256];
}

// ---------------- tf32 tensor-core GEMM, 3-stage cp.async pipeline ----------------
// Tile: BM=128, BN=64, BK=16.  8 warps as 4(M) x 2(N), warp tile 32x32.
// Both A and B fragments: raw fp32 bits (HW truncates to tf32) -- no cvt in loop.
// One __syncthreads per k-iter (3-stage rotation makes the single barrier safe).
// MODE 0: A=value, W=Wv   -> scatter into g_vt [b][h][pos][c]
// MODE 1: A=query, W=g_Wf -> g_P row-major
// MODE 2: A=g_tmp, W=Wout -> Cout = acc + bias + addin (residual)
template<int MODE>
__global__ __launch_bounds__(256)
void gemm_tc(const float* __restrict__ Ain, const float* __restrict__ Win,
             const float* __restrict__ biasin, const float* __restrict__ addin,
             float* __restrict__ Cout, int N)
{
    constexpr int K = D;
    const float* A    = (MODE == 2) ? g_tmp : Ain;
    const float* W    = (MODE == 1) ? g_Wf  : Win;
    const float* bias = (MODE == 1) ? g_bf  : biasin;

    __shared__ float As[3][128][20];   // [stage][m][k], stride 20 -> conflict-free
    __shared__ float Bs[3][16][72];    // [stage][k][n], stride 72 -> conflict-free

    const int tid  = threadIdx.x;
    const int warp = tid >> 5;
    const int lane = tid & 31;
    const int wm   = (warp & 3) * 32;
    const int wn   = (warp >> 2) * 32;
    const int m0   = blockIdx.x * 128;
    const int n0   = blockIdx.y * 64;

    const int ar = tid >> 2;   // 0..63 (and +64)
    const int aq = tid & 3;
    const int br = tid >> 4;   // 0..15
    const int bc = tid & 15;

    float c[2][4][4];
    #pragma unroll
    for (int mf = 0; mf < 2; ++mf)
        #pragma unroll
        for (int nf = 0; nf < 4; ++nf)
            #pragma unroll
            for (int i = 0; i < 4; ++i) c[mf][nf][i] = 0.f;

    auto load_stage = [&](int kt, int buf) {
        const int kk = kt * 16;
        cp16(&As[buf][ar][aq * 4],      A + (size_t)(m0 + ar) * K + kk + aq * 4);
        cp16(&As[buf][ar + 64][aq * 4], A + (size_t)(m0 + ar + 64) * K + kk + aq * 4);
        cp16(&Bs[buf][br][bc * 4],      W + (size_t)(kk + br) * N + n0 + bc * 4);
        asm volatile("cp.async.commit_group;" ::: "memory");
    };

    load_stage(0, 0);
    load_stage(1, 1);

    for (int kt = 0; kt < 16; ++kt) {
        const int buf = kt % 3;
        if (kt < 15) {
            asm volatile("cp.async.wait_group 1;" ::: "memory");
        } else {
            asm volatile("cp.async.wait_group 0;" ::: "memory");
        }
        __syncthreads();

        #pragma unroll
        for (int kc = 0; kc < 16; kc += 8) {
            uint32_t a[2][4], b[4][2];
            const int arow = wm + (lane >> 2);
            const int acol = kc + (lane & 3);
            #pragma unroll
            for (int mf = 0; mf < 2; ++mf) {
                const int r0 = arow + mf * 16;
                a[mf][0] = __float_as_uint(As[buf][r0    ][acol    ]);
                a[mf][1] = __float_as_uint(As[buf][r0 + 8][acol    ]);
                a[mf][2] = __float_as_uint(As[buf][r0    ][acol + 4]);
                a[mf][3] = __float_as_uint(As[buf][r0 + 8][acol + 4]);
            }
            #pragma unroll
            for (int nf = 0; nf < 4; ++nf) {
                const int nn = wn + nf * 8 + (lane >> 2);
                b[nf][0] = __float_as_uint(Bs[buf][acol    ][nn]);
                b[nf][1] = __float_as_uint(Bs[buf][acol + 4][nn]);
            }
            #pragma unroll
            for (int mf = 0; mf < 2; ++mf)
                #pragma unroll
                for (int nf = 0; nf < 4; ++nf)
                    mma_tf32(c[mf][nf][0], c[mf][nf][1], c[mf][nf][2], c[mf][nf][3],
                             a[mf][0], a[mf][1], a[mf][2], a[mf][3],
                             b[nf][0], b[nf][1]);
        }

        if (kt + 2 < 16) load_stage(kt + 2, (kt + 2) % 3);
    }

    // epilogue
    #pragma unroll
    for (int mf = 0; mf < 2; ++mf) {
        #pragma unroll
        for (int nf = 0; nf < 4; ++nf) {
            const int cb = n0 + wn + nf * 8 + 2 * (lane & 3);
            const float2 b2 = *reinterpret_cast<const float2*>(bias + cb);
            #pragma unroll
            for (int half = 0; half < 2; ++half) {
                const int row = m0 + wm + mf * 16 + (lane >> 2) + half * 8;
                const float v0 = c[mf][nf][half * 2 + 0] + b2.x;
                const float v1 = c[mf][nf][half * 2 + 1] + b2.y;
                if (MODE == 0) {
                    const int bb  = row / NQ;
                    const int pos = row - bb * NQ;
                    float2* dst = reinterpret_cast<float2*>(
                        g_vt + ((size_t)(bb * NH + (cb >> 5)) * NQ + pos) * DH + (cb & 31));
                    *dst = make_float2(v0, v1);
                } else if (MODE == 1) {
                    *reinterpret_cast<float2*>(g_P + (size_t)row * NFUSED + cb)
                        = make_float2(v0, v1);
                } else {
                    const float2 q2 = *reinterpret_cast<const float2*>(
                        addin + (size_t)row * D + cb);
                    *reinterpret_cast<float2*>(Cout + (size_t)row * D + cb)
                        = make_float2(v0 + q2.x, v1 + q2.y);
                }
            }
        }
    }
}

// ---------------- fused softmax + coords + bilinear gather ----------------
// R3 structure (measured best).  min-6-blocks hint raises occupancy 56% -> 75%.
__global__ __launch_bounds__(256, 6)
void sample_kernel(const float* __restrict__ refp) {
    const int gwarp = blockIdx.x * 8 + (threadIdx.x >> 5);
    const int lane  = threadIdx.x & 31;
    if (gwarp >= MR * NH) return;
    const int h  = gwarp & 7;
    const int bq = gwarp >> 3;
    const int b  = (bq >= NQ);

    const float* Prow = g_P + (size_t)bq * NFUSED;
    const int i  = lane & 15;          // point index (lanes 16-31 mirror)
    const int il = i >> 2;

    // softmax over the 16 logits of this head
    float lg = Prow[256 + h * 16 + i];
    float mx = lg;
    #pragma unroll
    for (int off = 8; off; off >>= 1)
        mx = fmaxf(mx, __shfl_xor_sync(0xffffffffu, mx, off));
    float e = __expf(lg - mx);
    float ssum = e;
    #pragma unroll
    for (int off = 8; off; off >>= 1)
        ssum += __shfl_xor_sync(0xffffffffu, ssum, off);
    const float wgt = e / ssum;

    // pixel coords for this lane's point
    const float2 off2 = *reinterpret_cast<const float2*>(Prow + h * 32 + i * 2);
    const float2 ref2 = *reinterpret_cast<const float2*>(refp + (size_t)bq * 8 + il * 2);
    const float px = ref2.x * (float)c_LW[il] + off2.x - 0.5f;
    const float py = ref2.y * (float)c_LH[il] + off2.y - 0.5f;

    const int pgrp = lane >> 3;       // which point of the level this group does
    const int cq   = (lane & 7) * 4;  // channel quad
    const float* vb = g_vt + ((size_t)(b * NH + h) * NQ) * DH + cq;

    float4 acc = make_float4(0.f, 0.f, 0.f, 0.f);
    #pragma unroll
    for (int j = 0; j < 4; ++j) {     // j = level
        const int Wl = c_LW[j], Hl = c_LH[j], st = c_LS[j];
        const int p  = j * 4 + pgrp;
        const float sx = __shfl_sync(0xffffffffu, px,  p);
        const float sy = __shfl_sync(0xffffffffu, py,  p);
        const float sw = __shfl_sync(0xffffffffu, wgt, p);

        const float xf = floorf(sx), yf = floorf(sy);
        const int   x0 = (int)xf,    y0 = (int)yf;
        const float wx1 = sx - xf,   wy1 = sy - yf;
        const float wx0 = 1.f - wx1, wy0 = 1.f - wy1;
        const int x1 = x0 + 1, y1 = y0 + 1;
        const bool vx0 = (x0 >= 0) && (x0 < Wl);
        const bool vx1 = (x1 >= 0) && (x1 < Wl);
        const bool vy0 = (y0 >= 0) && (y0 < Hl);
        const bool vy1 = (y1 >= 0) && (y1 < Hl);

        const float w00 = sw * wy0 * wx0;
        const float w01 = sw * wy0 * wx1;
        const float w10 = sw * wy1 * wx0;
        const float w11 = sw * wy1 * wx1;

        float4 v00 = make_float4(0,0,0,0), v01 = v00, v10 = v00, v11 = v00;
        const float* r0 = vb + (size_t)(st + y0 * Wl) * DH;
        const float* r1 = vb + (size_t)(st + y1 * Wl) * DH;
        if (vy0 && vx0) v00 = *reinterpret_cast<const float4*>(r0 + (size_t)x0 * DH);
        if (vy0 && vx1) v01 = *reinterpret_cast<const float4*>(r0 + (size_t)x1 * DH);
        if (vy1 && vx0) v10 = *reinterpret_cast<const float4*>(r1 + (size_t)x0 * DH);
        if (vy1 && vx1) v11 = *reinterpret_cast<const float4*>(r1 + (size_t)x1 * DH);

        acc.x += w00 * v00.x + w01 * v01.x + w10 * v10.x + w11 * v11.x;
        acc.y += w00 * v00.y + w01 * v01.y + w10 * v10.y + w11 * v11.y;
        acc.z += w00 * v00.z + w01 * v01.z + w10 * v10.z + w11 * v11.z;
        acc.w += w00 * v00.w + w01 * v01.w + w10 * v10.w + w11 * v11.w;
    }

    // reduce across the 4 point-groups (lanes xor 8, 16)
    #pragma unroll
    for (int off = 8; off <= 16; off <<= 1) {
        acc.x += __shfl_xor_sync(0xffffffffu, acc.x, off);
        acc.y += __shfl_xor_sync(0xffffffffu, acc.y, off);
        acc.z += __shfl_xor_sync(0xffffffffu, acc.z, off);
        acc.w += __shfl_xor_sync(0xffffffffu, acc.w, off);
    }
    if (lane < 8)
        *reinterpret_cast<float4*>(g_tmp + (size_t)bq * D + h * DH + cq) = acc;
}

// ---------------- launch ----------------
extern "C" void kernel_launch(void* const* d_in, const int* in_sizes, int n_in,
                              void* d_out, int out_size) {
    const float* query = (const float*)d_in[0];
    const float* value = (const float*)d_in[1];
    const float* refp  = (const float*)d_in[2];
    const float* Wv   = (const float*)d_in[5];
    const float* bv   = (const float*)d_in[6];
    const float* Wo   = (const float*)d_in[7];
    const float* bo   = (const float*)d_in[8];
    const float* Wa   = (const float*)d_in[9];
    const float* ba   = (const float*)d_in[10];
    const float* Wout = (const float*)d_in[11];
    const float* bout = (const float*)d_in[12];
    float* out = (float*)d_out;

    pack_w_kernel<<<(D * NFUSED + 255) / 256, 256>>>(Wo, bo, Wa, ba);

    gemm_tc<0><<<dim3(MR / 128, 256 / 64), 256>>>(value, Wv, bv, nullptr, nullptr, 256);
    gemm_tc<1><<<dim3(MR / 128, NFUSED / 64), 256>>>(query, nullptr, nullptr, nullptr, nullptr, NFUSED);

    sample_kernel<<<MR * NH / 8, 256>>>(refp);

    gemm_tc<2><<<dim3(MR / 128, 256 / 64), 256>>>(nullptr, Wout, bout, query, out, 256);
}